// round 14
// baseline (speedup 1.0000x reference)
#include <cuda_runtime.h>
#include <cuda_fp16.h>
#include <cstdint>

// Problem constants
#define NN     8192
#define INDIM  256
#define DTOT   128      // OUT_DIM * HEADS
#define NCP    144      // padded GEMM N: 128 outputs + 2 denominators + 14 zero pad
#define MT     128      // M tile
#define KT     64       // K tile
#define NSPLIT 4        // split-K factor
#define KSPLIT 2048     // K per split
#define NKI    32       // K iterations per split

// -------- static device scratch (no allocations allowed) --------
__device__ float     g_h[NN * DTOT];            // 4 MB   h = x @ W^T (fp32)
__device__ float     g_er[2 * NN];              // er per head
__device__ unsigned  g_maxkey[2];               // encoded global max of er per head
__device__ __half    g_g[NCP * NN];             // 2.25 MB  G^T fp16 [NCP][NN]
__device__ float     g_part[(size_t)NSPLIT * NN * NCP];  // 18.9 MB split-K partials

__device__ __forceinline__ uint32_t smem_u32(const void* p) {
    uint32_t a;
    asm("{ .reg .u64 t; cvta.to.shared.u64 t, %1; cvt.u32.u64 %0, t; }" : "=r"(a) : "l"(p));
    return a;
}
#define SWZ(off) ((off) ^ (((off) >> 3) & 0x70))

// ordered-uint encoding for float atomicMax
__device__ __forceinline__ unsigned enc_f(float f) {
    unsigned b = __float_as_uint(f);
    return (b & 0x80000000u) ? ~b : (b | 0x80000000u);
}
__device__ __forceinline__ float dec_f(unsigned k) {
    return (k & 0x80000000u) ? __uint_as_float(k & 0x7FFFFFFFu) : __uint_as_float(~k);
}

// ======================= k1: h = x @ W^T (fp32, register tiled) =======================
__global__ void __launch_bounds__(256) k1_h_gemm(const float* __restrict__ x,
                                                const float* __restrict__ W) {
    if (blockIdx.x == 0 && threadIdx.x < 2) g_maxkey[threadIdx.x] = 0u;  // reset for k2a

    __shared__ __align__(16) float xs[32][132];  // k-major [kk][i]
    __shared__ __align__(16) float ws[32][68];   // k-major [kk][c]
    int tid = threadIdx.x;
    int mtile = blockIdx.x >> 1, ntile = blockIdx.x & 1;
    int i0 = mtile * 128, n0 = ntile * 64;
    int tx = tid & 15, ty = tid >> 4;
    int r0 = ty * 8, c0 = tx * 4;

    float acc[8][4];
#pragma unroll
    for (int m = 0; m < 8; ++m)
#pragma unroll
        for (int n = 0; n < 4; ++n) acc[m][n] = 0.f;

    for (int kc = 0; kc < 8; ++kc) {
        int k0 = kc * 32;
#pragma unroll
        for (int i = 0; i < 4; ++i) {          // x tile: 1024 float4
            int q = tid + i * 256;
            int r = q >> 3, c4 = q & 7;
            float4 v = *(const float4*)(x + (size_t)(i0 + r) * INDIM + k0 + c4 * 4);
            xs[c4 * 4 + 0][r] = v.x; xs[c4 * 4 + 1][r] = v.y;
            xs[c4 * 4 + 2][r] = v.z; xs[c4 * 4 + 3][r] = v.w;
        }
#pragma unroll
        for (int i = 0; i < 2; ++i) {          // W tile: 512 float4
            int q = tid + i * 256;
            int r = q >> 3, c4 = q & 7;
            float4 v = *(const float4*)(W + (size_t)(n0 + r) * INDIM + k0 + c4 * 4);
            ws[c4 * 4 + 0][r] = v.x; ws[c4 * 4 + 1][r] = v.y;
            ws[c4 * 4 + 2][r] = v.z; ws[c4 * 4 + 3][r] = v.w;
        }
        __syncthreads();
#pragma unroll
        for (int kk = 0; kk < 32; ++kk) {
            float4 a0 = *(const float4*)&xs[kk][r0];
            float4 a1 = *(const float4*)&xs[kk][r0 + 4];
            float4 bv = *(const float4*)&ws[kk][c0];
            float a[8] = {a0.x, a0.y, a0.z, a0.w, a1.x, a1.y, a1.z, a1.w};
            float b[4] = {bv.x, bv.y, bv.z, bv.w};
#pragma unroll
            for (int m = 0; m < 8; ++m)
#pragma unroll
                for (int n = 0; n < 4; ++n) acc[m][n] += a[m] * b[n];
        }
        __syncthreads();
    }
#pragma unroll
    for (int m = 0; m < 8; ++m) {
        float4 v = make_float4(acc[m][0], acc[m][1], acc[m][2], acc[m][3]);
        *(float4*)(g_h + (size_t)(i0 + r0 + m) * DTOT + n0 + c0) = v;
    }
}

// ======================= k2a: er[j,h] + global max per head =======================
__global__ void __launch_bounds__(256) k2a_er(const float* __restrict__ attn_r) {
    int tid = threadIdx.x, lane = tid & 31, wid = tid >> 5;
    int j = blockIdx.x * 256 + tid;
    const float* hp = g_h + (size_t)j * DTOT;
    float er0 = 0.f, er1 = 0.f;
#pragma unroll
    for (int d = 0; d < 64; ++d) {
        er0 += hp[d]      * attn_r[d];
        er1 += hp[64 + d] * attn_r[64 + d];
    }
    g_er[j] = er0;
    g_er[NN + j] = er1;

    float m0 = er0, m1 = er1;
#pragma unroll
    for (int o = 16; o; o >>= 1) {
        m0 = fmaxf(m0, __shfl_xor_sync(0xFFFFFFFFu, m0, o));
        m1 = fmaxf(m1, __shfl_xor_sync(0xFFFFFFFFu, m1, o));
    }
    __shared__ float s0[8], s1[8];
    if (lane == 0) { s0[wid] = m0; s1[wid] = m1; }
    __syncthreads();
    if (tid == 0) {
#pragma unroll
        for (int w = 1; w < 8; ++w) { m0 = fmaxf(m0, s0[w]); m1 = fmaxf(m1, s1[w]); }
        m0 = fmaxf(m0, s0[0]); m1 = fmaxf(m1, s1[0]);
        atomicMax(&g_maxkey[0], enc_f(m0));
        atomicMax(&g_maxkey[1], enc_f(m1));
    }
}

// ======================= k2b: G^T = exp(er - max) * h  (fp16) =======================
__global__ void __launch_bounds__(256) k2b_build_g() {
    int j = blockIdx.x * 256 + threadIdx.x;
    float m0 = dec_f(g_maxkey[0]), m1 = dec_f(g_maxkey[1]);
    float E0 = expf(g_er[j] - m0);
    float E1 = expf(g_er[NN + j] - m1);
    const float* hp = g_h + (size_t)j * DTOT;
    float hr[128];
#pragma unroll
    for (int i = 0; i < 32; ++i) {
        float4 v = *(const float4*)(hp + i * 4);
        hr[i * 4 + 0] = v.x; hr[i * 4 + 1] = v.y; hr[i * 4 + 2] = v.z; hr[i * 4 + 3] = v.w;
    }
#pragma unroll
    for (int c = 0; c < 128; ++c) {
        float v = (c < 64 ? E0 : E1) * hr[c];
        g_g[(size_t)c * NN + j] = __float2half(v);
    }
    g_g[(size_t)128 * NN + j] = __float2half(E0);
    g_g[(size_t)129 * NN + j] = __float2half(E1);
#pragma unroll
    for (int c = 130; c < NCP; ++c) g_g[(size_t)c * NN + j] = __float2half(0.f);
}

// ======================= k3: [num|den] = f16(adj) @ G =======================
// 384 threads, warp grid 4(M) x 3(N): warp = 32 rows x 48 cols (acc 48 regs).
// Stage: B fp16 SW128 (144x128B = 18432) then A int8 (128 rows x 80B = 10240).
#define NTHR3   384
#define BBYTES  18432
#define APITCH8 80
#define ABYTES8 10240
#define STAGEB  (BBYTES + ABYTES8)   // 28672
#define NSTG    3
#define SMEM3   (NSTG * STAGEB)      // 86016

__device__ __forceinline__ void stage_loadB(uint32_t Bb, int j0, int tid) {
#pragma unroll
    for (int i = 0; i < 3; ++i) {             // 1152 = 3 * 384 chunks exactly
        int q = tid + i * NTHR3;
        int n = q >> 3, c = q & 7;
        uint32_t dst = Bb + SWZ((uint32_t)(n * 128 + c * 16));
        const void* src = (const char*)g_g + ((size_t)n * NN + j0) * 2 + c * 16;
        asm volatile("cp.async.cg.shared.global [%0], [%1], 16;" :: "r"(dst), "l"(src));
    }
    asm volatile("cp.async.commit_group;" ::: "memory");
}

// pack byte0 of 4 ints (values 0/1) into one u32
__device__ __forceinline__ uint32_t pack4(int4 v) {
    uint32_t t0, t1, d;
    asm("prmt.b32 %0, %1, %2, 0x0040;" : "=r"(t0) : "r"((uint32_t)v.x), "r"((uint32_t)v.y));
    asm("prmt.b32 %0, %1, %2, 0x0040;" : "=r"(t1) : "r"((uint32_t)v.z), "r"((uint32_t)v.w));
    asm("prmt.b32 %0, %1, %2, 0x5410;" : "=r"(d)  : "r"(t0), "r"(t1));
    return d;
}

// A producer: 2048 int4 chunks over 384 threads (guarded, 6 rounds)
__device__ __forceinline__ void stage_loadA(uint32_t Ab, const int* __restrict__ adj,
                                            int i0, int j0, int tid) {
#pragma unroll
    for (int i = 0; i < 6; ++i) {
        int q = tid + i * NTHR3;
        if (q < 2048) {
            int r = q >> 4, ch = q & 15;
            int4 v = *(const int4*)(adj + (size_t)(i0 + r) * NN + j0 + ch * 4);
            uint32_t p = pack4(v);
            asm volatile("st.shared.u32 [%0], %1;"
                         :: "r"(Ab + (uint32_t)(r * APITCH8 + ch * 4)), "r"(p));
        }
    }
}

// one k-step: A frags from int8 smem, B frags via 3x ldmatrix.x4, 12 MMAs
__device__ __forceinline__ void do_kstep(uint32_t Bb, uint32_t abase, int ks,
                                         float acc[2][6][4], const uint32_t brow[3]) {
    uint32_t a[2][4];
#pragma unroll
    for (int mf = 0; mf < 2; ++mf)
#pragma unroll
        for (int q = 0; q < 4; ++q) {
            uint32_t off = abase + (uint32_t)(mf * 16 * APITCH8 + (q & 1) * 8 * APITCH8 +
                                              (q >> 1) * 8 + ks * 16);
            uint32_t v, t;
            asm("ld.shared.u16 %0, [%1];" : "=r"(v) : "r"(off));
            asm("prmt.b32 %0, %1, 0, 0x4140;" : "=r"(t) : "r"(v));
            a[mf][q] = t * 0x3C00u;
        }
    uint32_t kb = (uint32_t)(ks * 32);
    uint32_t b[6][2];
#pragma unroll
    for (int g4 = 0; g4 < 3; ++g4) {
        uint32_t bd = Bb + SWZ(brow[g4] + kb);
        asm volatile("ldmatrix.sync.aligned.m8n8.x4.shared.b16 {%0,%1,%2,%3}, [%4];"
            : "=r"(b[2 * g4][0]), "=r"(b[2 * g4][1]),
              "=r"(b[2 * g4 + 1][0]), "=r"(b[2 * g4 + 1][1]) : "r"(bd));
    }
#pragma unroll
    for (int mf = 0; mf < 2; ++mf)
#pragma unroll
        for (int nf = 0; nf < 6; ++nf)
            asm volatile(
                "mma.sync.aligned.m16n8k16.row.col.f32.f16.f16.f32 "
                "{%0,%1,%2,%3}, {%4,%5,%6,%7}, {%8,%9}, {%0,%1,%2,%3};"
                : "+f"(acc[mf][nf][0]), "+f"(acc[mf][nf][1]),
                  "+f"(acc[mf][nf][2]), "+f"(acc[mf][nf][3])
                : "r"(a[mf][0]), "r"(a[mf][1]), "r"(a[mf][2]), "r"(a[mf][3]),
                  "r"(b[nf][0]), "r"(b[nf][1]));
}

__global__ void __launch_bounds__(NTHR3, 2) k3_adj_gemm(const int* __restrict__ adj) {
    extern __shared__ char sm3[];
    uint32_t sb = smem_u32(sm3);
    int tid = threadIdx.x, lane = tid & 31, wid = tid >> 5;
    int wm = wid & 3, wn = wid >> 2;          // 4 (M) x 3 (N) warps
    int lt = lane >> 3, lr = lane & 7;
    int mtile = blockIdx.x >> 2, sp = blockIdx.x & 3;
    int i0 = mtile * MT, jb = sp * KSPLIT;

    // A consumer per-lane base (within stage A region)
    uint32_t aoff8 = (uint32_t)((wm * 32 + (lane >> 2)) * APITCH8 + (lane & 3) * 2);
    // B ldmatrix per-lane offsets (pre-swizzle): 3 groups of 16 cols = 48 cols per warp
    uint32_t brow[3];
#pragma unroll
    for (int g4 = 0; g4 < 3; ++g4)
        brow[g4] = (uint32_t)((wn * 48 + g4 * 16 + (lt >> 1) * 8 + lr) * 128 + (lt & 1) * 16);

    float acc[2][6][4];
#pragma unroll
    for (int mf = 0; mf < 2; ++mf)
#pragma unroll
        for (int nf = 0; nf < 6; ++nf)
#pragma unroll
            for (int q = 0; q < 4; ++q) acc[mf][nf][q] = 0.f;

    // prologue: stages 0,1 (B async + A pack)
#pragma unroll
    for (int s = 0; s < 2; ++s) {
        stage_loadB(sb + s * STAGEB, jb + s * KT, tid);
        stage_loadA(sb + s * STAGEB + BBYTES, adj, i0, jb + s * KT, tid);
    }

    for (int it = 0; it < NKI; ++it) {
        if (it == NKI - 1)
            asm volatile("cp.async.wait_group 0;" ::: "memory");
        else
            asm volatile("cp.async.wait_group 1;" ::: "memory");
        __syncthreads();

        bool ld = (it + 2 < NKI);
        uint32_t Sw = sb + ((it + 2) % 3) * STAGEB;           // write stage
        if (ld) stage_loadB(Sw, jb + (it + 2) * KT, tid);

        uint32_t Sr = sb + (it % 3) * STAGEB;                 // read stage
        uint32_t abase = Sr + BBYTES + aoff8;
        do_kstep(Sr, abase, 0, acc, brow);
        do_kstep(Sr, abase, 1, acc, brow);
        do_kstep(Sr, abase, 2, acc, brow);
        do_kstep(Sr, abase, 3, acc, brow);

        // A producer for stage it+2 after compute (staging regs live while frags are dead)
        if (ld) stage_loadA(Sw + BBYTES, adj, i0, jb + (it + 2) * KT, tid);
    }

    // epilogue: store split-K partials
    int r0 = i0 + wm * 32 + (lane >> 2);
    int c0 = wn * 48 + (lane & 3) * 2;
    float* base = g_part + (size_t)sp * NN * NCP;
#pragma unroll
    for (int mf = 0; mf < 2; ++mf)
#pragma unroll
        for (int nf = 0; nf < 6; ++nf) {
            int row = r0 + mf * 16, col = c0 + nf * 8;
            *(float2*)(base + (size_t)row * NCP + col) =
                make_float2(acc[mf][nf][0], acc[mf][nf][1]);
            *(float2*)(base + (size_t)(row + 8) * NCP + col) =
                make_float2(acc[mf][nf][2], acc[mf][nf][3]);
        }
}

// ======================= k4: combine splits + divide =======================
__global__ void __launch_bounds__(256) k4_finalize(float* __restrict__ out) {
    int g = blockIdx.x * 256 + threadIdx.x;   // over 8192*128
    int i = g >> 7, c = g & 127;
    int hh = c >> 6;
    float num = 0.f, den = 0.f;
#pragma unroll
    for (int s = 0; s < NSPLIT; ++s) {
        const float* p = g_part + ((size_t)s * NN + i) * NCP;
        num += p[c];
        den += p[128 + hh];
    }
    out[g] = num / den;
}

// ======================= launch =======================
extern "C" void kernel_launch(void* const* d_in, const int* in_sizes, int n_in,
                              void* d_out, int out_size) {
    (void)in_sizes; (void)n_in; (void)out_size;
    const float* x      = (const float*)d_in[0];
    const int*   adj    = (const int*)d_in[1];
    const float* W      = (const float*)d_in[2];
    // d_in[3] = attn_l : cancels in the softmax over j — unused
    const float* attn_r = (const float*)d_in[4];
    float* out = (float*)d_out;

    cudaFuncSetAttribute(k3_adj_gemm, cudaFuncAttributeMaxDynamicSharedMemorySize, SMEM3);

    k1_h_gemm<<<128, 256>>>(x, W);
    k2a_er<<<32, 256>>>(attn_r);
    k2b_build_g<<<32, 256>>>();
    k3_adj_gemm<<<256, NTHR3, SMEM3>>>(adj);
    k4_finalize<<<4096, 256>>>(out);
}

// round 15
// speedup vs baseline: 1.2688x; 1.2688x over previous
#include <cuda_runtime.h>
#include <cuda_fp16.h>
#include <cstdint>

// Problem constants
#define NN     8192
#define INDIM  256
#define DTOT   128      // OUT_DIM * HEADS
#define NCP    144      // padded GEMM N: 128 outputs + 2 denominators + 14 zero pad
#define MT     128      // M tile
#define KT     64       // K tile
#define NSPLIT 4        // split-K factor
#define KSPLIT 2048     // K per split
#define NKI    32       // K iterations per split

// -------- static device scratch (no allocations allowed) --------
__device__ float     g_h[NN * DTOT];            // 4 MB   h = x @ W^T (fp32)
__device__ float     g_er[2 * NN];              // er per head
__device__ unsigned  g_maxkey[2];               // encoded global max of er per head
__device__ __half    g_g[NCP * NN];             // 2.25 MB  G^T fp16 [NCP][NN]
__device__ float     g_part[(size_t)NSPLIT * NN * NCP];  // 18.9 MB split-K partials
__device__ __half    g_xh[NN * INDIM];          // 4 MB  x hi fp16
__device__ __half    g_xl[NN * INDIM];          // 4 MB  x lo fp16
__device__ __half    g_wh[DTOT * INDIM];        // 64 KB W hi fp16
__device__ __half    g_wl[DTOT * INDIM];        // 64 KB W lo fp16

__device__ __forceinline__ uint32_t smem_u32(const void* p) {
    uint32_t a;
    asm("{ .reg .u64 t; cvta.to.shared.u64 t, %1; cvt.u32.u64 %0, t; }" : "=r"(a) : "l"(p));
    return a;
}
#define SWZ(off) ((off) ^ (((off) >> 3) & 0x70))

// ordered-uint encoding for float atomicMax
__device__ __forceinline__ unsigned enc_f(float f) {
    unsigned b = __float_as_uint(f);
    return (b & 0x80000000u) ? ~b : (b | 0x80000000u);
}
__device__ __forceinline__ float dec_f(unsigned k) {
    return (k & 0x80000000u) ? __uint_as_float(k & 0x7FFFFFFFu) : __uint_as_float(~k);
}

// ======================= k0: split x, W into fp16 hi/lo =======================
__global__ void __launch_bounds__(256) k0_convert(const float* __restrict__ x,
                                                 const float* __restrict__ W) {
    int g = blockIdx.x * 256 + threadIdx.x;          // over 2M/4 float4s of x
    if (g == 0) { g_maxkey[0] = 0u; g_maxkey[1] = 0u; }
    {
        float4 v = ((const float4*)x)[g];
        __half h0 = __float2half(v.x), h1 = __float2half(v.y),
               h2 = __float2half(v.z), h3 = __float2half(v.w);
        uint2 hh = make_uint2((uint32_t)__half_as_ushort(h0) | ((uint32_t)__half_as_ushort(h1) << 16),
                              (uint32_t)__half_as_ushort(h2) | ((uint32_t)__half_as_ushort(h3) << 16));
        ((uint2*)g_xh)[g] = hh;
        __half l0 = __float2half(v.x - __half2float(h0));
        __half l1 = __float2half(v.y - __half2float(h1));
        __half l2 = __float2half(v.z - __half2float(h2));
        __half l3 = __float2half(v.w - __half2float(h3));
        uint2 ll = make_uint2((uint32_t)__half_as_ushort(l0) | ((uint32_t)__half_as_ushort(l1) << 16),
                              (uint32_t)__half_as_ushort(l2) | ((uint32_t)__half_as_ushort(l3) << 16));
        ((uint2*)g_xl)[g] = ll;
    }
    if (g < DTOT * INDIM / 4) {
        float4 v = ((const float4*)W)[g];
        __half h0 = __float2half(v.x), h1 = __float2half(v.y),
               h2 = __float2half(v.z), h3 = __float2half(v.w);
        uint2 hh = make_uint2((uint32_t)__half_as_ushort(h0) | ((uint32_t)__half_as_ushort(h1) << 16),
                              (uint32_t)__half_as_ushort(h2) | ((uint32_t)__half_as_ushort(h3) << 16));
        ((uint2*)g_wh)[g] = hh;
        __half l0 = __float2half(v.x - __half2float(h0));
        __half l1 = __float2half(v.y - __half2float(h1));
        __half l2 = __float2half(v.z - __half2float(h2));
        __half l3 = __float2half(v.w - __half2float(h3));
        uint2 ll = make_uint2((uint32_t)__half_as_ushort(l0) | ((uint32_t)__half_as_ushort(l1) << 16),
                              (uint32_t)__half_as_ushort(l2) | ((uint32_t)__half_as_ushort(l3) << 16));
        ((uint2*)g_wl)[g] = ll;
    }
}

// ======================= k1: h = x @ W^T (fp16 hi/lo tensor cores) =======================
// grid 128 = 64 m-tiles x 2 n-tiles. CTA: 128 rows x 64 cols, K=256 all resident.
// smem: Wh[k] k*8192 | Wl 32768+k*8192 | Xh 65536+k*16384 | Xl 131072+k*16384  (192 KB)
#define K1_SMEM 196608
__global__ void __launch_bounds__(256) k1_h_gemm(const int dummy) {
    extern __shared__ char s1[];
    uint32_t sb = smem_u32(s1);
    int tid = threadIdx.x, lane = tid & 31, wid = tid >> 5;
    int wm = wid & 3, wn = wid >> 2;      // 4(M) x 2(N)
    int lt = lane >> 3, lr = lane & 7;
    int mtile = blockIdx.x >> 1, ntile = blockIdx.x & 1;
    int i0 = mtile * 128, n0 = ntile * 64;

    // W tiles: per k-chunk 64 rows x 128B, SW128 (hi and lo)
#pragma unroll
    for (int i = 0; i < 8; ++i) {
        int q = tid + i * 256;                  // 2048 chunks
        int k = q >> 9, r = (q >> 3) & 63, c = q & 7;
        uint32_t sw = SWZ((uint32_t)(r * 128 + c * 16));
        const void* sh = (const char*)g_wh + ((size_t)(n0 + r) * INDIM + k * 64 + c * 8) * 2;
        const void* sl = (const char*)g_wl + ((size_t)(n0 + r) * INDIM + k * 64 + c * 8) * 2;
        asm volatile("cp.async.cg.shared.global [%0], [%1], 16;" :: "r"(sb + k * 8192 + sw), "l"(sh));
        asm volatile("cp.async.cg.shared.global [%0], [%1], 16;" :: "r"(sb + 32768 + k * 8192 + sw), "l"(sl));
    }
    // X tiles: per k-chunk 128 rows x 128B, SW128 (hi and lo)
#pragma unroll
    for (int i = 0; i < 16; ++i) {
        int q = tid + i * 256;                  // 4096 chunks
        int k = q >> 10, r = (q >> 3) & 127, c = q & 7;
        uint32_t sw = SWZ((uint32_t)(r * 128 + c * 16));
        const void* sh = (const char*)g_xh + ((size_t)(i0 + r) * INDIM + k * 64 + c * 8) * 2;
        const void* sl = (const char*)g_xl + ((size_t)(i0 + r) * INDIM + k * 64 + c * 8) * 2;
        asm volatile("cp.async.cg.shared.global [%0], [%1], 16;" :: "r"(sb + 65536 + k * 16384 + sw), "l"(sh));
        asm volatile("cp.async.cg.shared.global [%0], [%1], 16;" :: "r"(sb + 131072 + k * 16384 + sw), "l"(sl));
    }
    asm volatile("cp.async.commit_group;" ::: "memory");
    asm volatile("cp.async.wait_group 0;" ::: "memory");
    __syncthreads();

    // fragment lane offsets (proven R7 formulas)
    uint32_t arow[2], brow[2];
#pragma unroll
    for (int mf = 0; mf < 2; ++mf)
        arow[mf] = (uint32_t)((wm * 32 + mf * 16 + (lt & 1) * 8 + lr) * 128 + (lt >> 1) * 16);
#pragma unroll
    for (int g4 = 0; g4 < 2; ++g4)
        brow[g4] = (uint32_t)((wn * 32 + g4 * 16 + (lt >> 1) * 8 + lr) * 128 + (lt & 1) * 16);

    float acc[2][4][4];
#pragma unroll
    for (int mf = 0; mf < 2; ++mf)
#pragma unroll
        for (int nf = 0; nf < 4; ++nf)
#pragma unroll
            for (int q = 0; q < 4; ++q) acc[mf][nf][q] = 0.f;

#pragma unroll
    for (int kc = 0; kc < 4; ++kc) {
        uint32_t Wh = sb + kc * 8192, Wl = sb + 32768 + kc * 8192;
        uint32_t Xh = sb + 65536 + kc * 16384, Xl = sb + 131072 + kc * 16384;
#pragma unroll
        for (int s = 0; s < 4; ++s) {
            uint32_t kb = (uint32_t)(s * 32);
            uint32_t ah[2][4], al[2][4];
#pragma unroll
            for (int mf = 0; mf < 2; ++mf) {
                asm volatile("ldmatrix.sync.aligned.m8n8.x4.shared.b16 {%0,%1,%2,%3}, [%4];"
                    : "=r"(ah[mf][0]), "=r"(ah[mf][1]), "=r"(ah[mf][2]), "=r"(ah[mf][3])
                    : "r"(Xh + SWZ(arow[mf] + kb)));
                asm volatile("ldmatrix.sync.aligned.m8n8.x4.shared.b16 {%0,%1,%2,%3}, [%4];"
                    : "=r"(al[mf][0]), "=r"(al[mf][1]), "=r"(al[mf][2]), "=r"(al[mf][3])
                    : "r"(Xl + SWZ(arow[mf] + kb)));
            }
            uint32_t bh[4][2], bl[4][2];
#pragma unroll
            for (int g4 = 0; g4 < 2; ++g4) {
                asm volatile("ldmatrix.sync.aligned.m8n8.x4.shared.b16 {%0,%1,%2,%3}, [%4];"
                    : "=r"(bh[2 * g4][0]), "=r"(bh[2 * g4][1]),
                      "=r"(bh[2 * g4 + 1][0]), "=r"(bh[2 * g4 + 1][1])
                    : "r"(Wh + SWZ(brow[g4] + kb)));
                asm volatile("ldmatrix.sync.aligned.m8n8.x4.shared.b16 {%0,%1,%2,%3}, [%4];"
                    : "=r"(bl[2 * g4][0]), "=r"(bl[2 * g4][1]),
                      "=r"(bl[2 * g4 + 1][0]), "=r"(bl[2 * g4 + 1][1])
                    : "r"(Wl + SWZ(brow[g4] + kb)));
            }
#define K1MMA(AF, BF)                                                                   \
            asm volatile("mma.sync.aligned.m16n8k16.row.col.f32.f16.f16.f32 "           \
                "{%0,%1,%2,%3}, {%4,%5,%6,%7}, {%8,%9}, {%0,%1,%2,%3};"                 \
                : "+f"(acc[mf][nf][0]), "+f"(acc[mf][nf][1]),                           \
                  "+f"(acc[mf][nf][2]), "+f"(acc[mf][nf][3])                            \
                : "r"(AF[mf][0]), "r"(AF[mf][1]), "r"(AF[mf][2]), "r"(AF[mf][3]),       \
                  "r"(BF[nf][0]), "r"(BF[nf][1]))
#pragma unroll
            for (int mf = 0; mf < 2; ++mf)
#pragma unroll
                for (int nf = 0; nf < 4; ++nf) {
                    K1MMA(ah, bh);
                    K1MMA(al, bh);
                    K1MMA(ah, bl);
                }
#undef K1MMA
        }
    }

    int r0 = i0 + wm * 32 + (lane >> 2);
    int c0 = n0 + wn * 32 + (lane & 3) * 2;
#pragma unroll
    for (int mf = 0; mf < 2; ++mf)
#pragma unroll
        for (int nf = 0; nf < 4; ++nf) {
            int row = r0 + mf * 16, col = c0 + nf * 8;
            *(float2*)(g_h + (size_t)row * DTOT + col) =
                make_float2(acc[mf][nf][0], acc[mf][nf][1]);
            *(float2*)(g_h + (size_t)(row + 8) * DTOT + col) =
                make_float2(acc[mf][nf][2], acc[mf][nf][3]);
        }
}

// ======================= k2a: er[j,h] + global max per head =======================
__global__ void __launch_bounds__(256) k2a_er(const float* __restrict__ attn_r) {
    int tid = threadIdx.x, lane = tid & 31, wid = tid >> 5;
    int j = blockIdx.x * 256 + tid;
    const float* hp = g_h + (size_t)j * DTOT;
    float er0 = 0.f, er1 = 0.f;
#pragma unroll
    for (int d = 0; d < 64; ++d) {
        er0 += hp[d]      * attn_r[d];
        er1 += hp[64 + d] * attn_r[64 + d];
    }
    g_er[j] = er0;
    g_er[NN + j] = er1;

    float m0 = er0, m1 = er1;
#pragma unroll
    for (int o = 16; o; o >>= 1) {
        m0 = fmaxf(m0, __shfl_xor_sync(0xFFFFFFFFu, m0, o));
        m1 = fmaxf(m1, __shfl_xor_sync(0xFFFFFFFFu, m1, o));
    }
    __shared__ float s0[8], s1[8];
    if (lane == 0) { s0[wid] = m0; s1[wid] = m1; }
    __syncthreads();
    if (tid == 0) {
#pragma unroll
        for (int w = 1; w < 8; ++w) { m0 = fmaxf(m0, s0[w]); m1 = fmaxf(m1, s1[w]); }
        m0 = fmaxf(m0, s0[0]); m1 = fmaxf(m1, s1[0]);
        atomicMax(&g_maxkey[0], enc_f(m0));
        atomicMax(&g_maxkey[1], enc_f(m1));
    }
}

// ======================= k2b: G^T = exp(er - max) * h  (fp16) =======================
__global__ void __launch_bounds__(256) k2b_build_g() {
    int j = blockIdx.x * 256 + threadIdx.x;
    float m0 = dec_f(g_maxkey[0]), m1 = dec_f(g_maxkey[1]);
    float E0 = expf(g_er[j] - m0);
    float E1 = expf(g_er[NN + j] - m1);
    const float* hp = g_h + (size_t)j * DTOT;
    float hr[128];
#pragma unroll
    for (int i = 0; i < 32; ++i) {
        float4 v = *(const float4*)(hp + i * 4);
        hr[i * 4 + 0] = v.x; hr[i * 4 + 1] = v.y; hr[i * 4 + 2] = v.z; hr[i * 4 + 3] = v.w;
    }
#pragma unroll
    for (int c = 0; c < 128; ++c) {
        float v = (c < 64 ? E0 : E1) * hr[c];
        g_g[(size_t)c * NN + j] = __float2half(v);
    }
    g_g[(size_t)128 * NN + j] = __float2half(E0);
    g_g[(size_t)129 * NN + j] = __float2half(E1);
#pragma unroll
    for (int c = 130; c < NCP; ++c) g_g[(size_t)c * NN + j] = __float2half(0.f);
}

// ======================= k3: [num|den] = f16(adj) @ G  (R9 structure, all cp.async) =======================
// per stage: A as raw int32, 128 rows x 272B pitch (34816 B) ; B fp16 SW128 144x128B (18432 B)
#define APITCH 272
#define ABYTES 34816
#define STAGEB 53248
#define NSTG   2
#define SMEM3  (NSTG * STAGEB)

__device__ __forceinline__ void stage_load(uint32_t Sb, const int* __restrict__ adj,
                                           int i0, int j0, int tid) {
    uint32_t Ab = Sb, Bb = Sb + ABYTES;
#pragma unroll
    for (int i = 0; i < 8; ++i) {
        int q = tid + i * 256;
        int r = q >> 4, ch = q & 15;
        uint32_t dst = Ab + (uint32_t)(r * APITCH + ch * 16);
        const void* src = adj + (size_t)(i0 + r) * NN + j0 + ch * 4;
        asm volatile("cp.async.cg.shared.global [%0], [%1], 16;" :: "r"(dst), "l"(src));
    }
#pragma unroll
    for (int i = 0; i < 5; ++i) {
        int q = tid + i * 256;
        if (q < NCP * 8) {
            int n = q >> 3, c = q & 7;
            uint32_t dst = Bb + SWZ((uint32_t)(n * 128 + c * 16));
            const void* src = (const char*)g_g + ((size_t)n * NN + j0) * 2 + c * 16;
            asm volatile("cp.async.cg.shared.global [%0], [%1], 16;" :: "r"(dst), "l"(src));
        }
    }
    asm volatile("cp.async.commit_group;" ::: "memory");
}

__device__ __forceinline__ void compute_iter(uint32_t Ab, uint32_t Bb,
                                             float acc[2][9][4],
                                             uint32_t aoff,
                                             const uint32_t brow4[4],
                                             uint32_t brow2) {
#pragma unroll
    for (int s = 0; s < 4; ++s) {
        uint32_t kb = s * 32;
        uint32_t ka = s * 64;
        uint32_t a[2][4];
#pragma unroll
        for (int mf = 0; mf < 2; ++mf) {
            uint32_t base = Ab + aoff + (uint32_t)(mf * 16 * APITCH) + ka;
            uint32_t x0, y0, x1, y1, x2, y2, x3, y3;
            asm("ld.shared.v2.u32 {%0,%1}, [%2];" : "=r"(x0), "=r"(y0) : "r"(base));
            asm("ld.shared.v2.u32 {%0,%1}, [%2];" : "=r"(x1), "=r"(y1) : "r"(base + 8 * APITCH));
            asm("ld.shared.v2.u32 {%0,%1}, [%2];" : "=r"(x2), "=r"(y2) : "r"(base + 32));
            asm("ld.shared.v2.u32 {%0,%1}, [%2];" : "=r"(x3), "=r"(y3) : "r"(base + 8 * APITCH + 32));
            a[mf][0] = (x0 | (y0 << 16)) * 0x3C00u;
            a[mf][1] = (x1 | (y1 << 16)) * 0x3C00u;
            a[mf][2] = (x2 | (y2 << 16)) * 0x3C00u;
            a[mf][3] = (x3 | (y3 << 16)) * 0x3C00u;
        }
        uint32_t b[9][2];
#pragma unroll
        for (int g4 = 0; g4 < 4; ++g4) {
            uint32_t bd = Bb + SWZ(brow4[g4] + kb);
            asm volatile("ldmatrix.sync.aligned.m8n8.x4.shared.b16 {%0,%1,%2,%3}, [%4];"
                : "=r"(b[2 * g4][0]), "=r"(b[2 * g4][1]),
                  "=r"(b[2 * g4 + 1][0]), "=r"(b[2 * g4 + 1][1]) : "r"(bd));
        }
        {
            uint32_t bd = Bb + SWZ(brow2 + kb);
            asm volatile("ldmatrix.sync.aligned.m8n8.x2.shared.b16 {%0,%1}, [%2];"
                : "=r"(b[8][0]), "=r"(b[8][1]) : "r"(bd));
        }
#pragma unroll
        for (int mf = 0; mf < 2; ++mf)
#pragma unroll
            for (int nf = 0; nf < 9; ++nf)
                asm volatile(
                    "mma.sync.aligned.m16n8k16.row.col.f32.f16.f16.f32 "
                    "{%0,%1,%2,%3}, {%4,%5,%6,%7}, {%8,%9}, {%0,%1,%2,%3};"
                    : "+f"(acc[mf][nf][0]), "+f"(acc[mf][nf][1]),
                      "+f"(acc[mf][nf][2]), "+f"(acc[mf][nf][3])
                    : "r"(a[mf][0]), "r"(a[mf][1]), "r"(a[mf][2]), "r"(a[mf][3]),
                      "r"(b[nf][0]), "r"(b[nf][1]));
    }
}

__global__ void __launch_bounds__(256, 2) k3_adj_gemm(const int* __restrict__ adj) {
    extern __shared__ char sm3[];
    uint32_t sb = smem_u32(sm3);
    int tid = threadIdx.x, lane = tid & 31, wid = tid >> 5;
    int wm = wid & 3, wn = wid >> 2;          // 4 (M) x 2 (N) warps
    int lt = lane >> 3, lr = lane & 7;
    int mtile = blockIdx.x >> 2, sp = blockIdx.x & 3;
    int i0 = mtile * MT, jb = sp * KSPLIT;

    uint32_t aoff = (uint32_t)((wm * 32 + (lane >> 2)) * APITCH + (lane & 3) * 8);
    uint32_t brow4[4], brow2;
#pragma unroll
    for (int g4 = 0; g4 < 4; ++g4)
        brow4[g4] = (uint32_t)((wn * 72 + g4 * 16 + (lt >> 1) * 8 + lr) * 128 + (lt & 1) * 16);
    brow2 = (uint32_t)((wn * 72 + 64 + lr) * 128 + (lt & 1) * 16);

    float acc[2][9][4];
#pragma unroll
    for (int mf = 0; mf < 2; ++mf)
#pragma unroll
        for (int nf = 0; nf < 9; ++nf)
#pragma unroll
            for (int q = 0; q < 4; ++q) acc[mf][nf][q] = 0.f;

    stage_load(sb + 0 * STAGEB, adj, i0, jb + 0 * KT, tid);
    stage_load(sb + 1 * STAGEB, adj, i0, jb + 1 * KT, tid);

    for (int it = 0; it < NKI; ++it) {
        if (it < NKI - 1)
            asm volatile("cp.async.wait_group 1;" ::: "memory");
        else
            asm volatile("cp.async.wait_group 0;" ::: "memory");
        __syncthreads();
        uint32_t Sb = sb + (it & 1) * STAGEB;
        compute_iter(Sb, Sb + ABYTES, acc, aoff, brow4, brow2);
        if (it + 2 < NKI) {
            __syncthreads();   // all warps done reading this buffer
            stage_load(Sb, adj, i0, jb + (it + 2) * KT, tid);
        }
    }

    int r0 = i0 + wm * 32 + (lane >> 2);
    int c0 = wn * 72 + (lane & 3) * 2;
    float* base = g_part + (size_t)sp * NN * NCP;
#pragma unroll
    for (int mf = 0; mf < 2; ++mf)
#pragma unroll
        for (int nf = 0; nf < 9; ++nf) {
            int row = r0 + mf * 16, col = c0 + nf * 8;
            *(float2*)(base + (size_t)row * NCP + col) =
                make_float2(acc[mf][nf][0], acc[mf][nf][1]);
            *(float2*)(base + (size_t)(row + 8) * NCP + col) =
                make_float2(acc[mf][nf][2], acc[mf][nf][3]);
        }
}

// ======================= k4: combine splits + divide =======================
__global__ void __launch_bounds__(256) k4_finalize(float* __restrict__ out) {
    int g = blockIdx.x * 256 + threadIdx.x;   // over 8192*128
    int i = g >> 7, c = g & 127;
    int hh = c >> 6;
    float num = 0.f, den = 0.f;
#pragma unroll
    for (int s = 0; s < NSPLIT; ++s) {
        const float* p = g_part + ((size_t)s * NN + i) * NCP;
        num += p[c];
        den += p[128 + hh];
    }
    out[g] = num / den;
}

// ======================= launch =======================
extern "C" void kernel_launch(void* const* d_in, const int* in_sizes, int n_in,
                              void* d_out, int out_size) {
    (void)in_sizes; (void)n_in; (void)out_size;
    const float* x      = (const float*)d_in[0];
    const int*   adj    = (const int*)d_in[1];
    const float* W      = (const float*)d_in[2];
    // d_in[3] = attn_l : cancels in the softmax over j — unused
    const float* attn_r = (const float*)d_in[4];
    float* out = (float*)d_out;

    cudaFuncSetAttribute(k1_h_gemm, cudaFuncAttributeMaxDynamicSharedMemorySize, K1_SMEM);
    cudaFuncSetAttribute(k3_adj_gemm, cudaFuncAttributeMaxDynamicSharedMemorySize, SMEM3);

    k0_convert<<<2048, 256>>>(x, W);
    k1_h_gemm<<<128, 256, K1_SMEM>>>(0);
    k2a_er<<<32, 256>>>(attn_r);
    k2b_build_g<<<32, 256>>>();
    k3_adj_gemm<<<256, 256, SMEM3>>>(adj);
    k4_finalize<<<4096, 256>>>(out);
}

// round 17
// speedup vs baseline: 1.4797x; 1.1662x over previous
#include <cuda_runtime.h>
#include <cuda_fp16.h>
#include <cstdint>

// Problem constants
#define NN     8192
#define INDIM  256
#define DTOT   128      // OUT_DIM * HEADS
#define NCP    144      // padded GEMM N: 128 outputs + 2 denominators + 14 zero pad
#define MT     128      // M tile
#define KT     64       // K tile
#define NSPLIT 4        // split-K factor
#define KSPLIT 2048     // K per split
#define NKI    32       // K iterations per split

// -------- static device scratch (no allocations allowed) --------
__device__ float     g_h[NN * DTOT];            // 4 MB   h = x @ W^T (fp32)
__device__ float     g_er[2 * NN];              // er per head
__device__ unsigned  g_maxkey[2];               // encoded global max of er per head
__device__ __half    g_g[NCP * NN];             // 2.25 MB  G^T fp16 [NCP][NN]
__device__ float     g_part[(size_t)NSPLIT * NN * NCP];  // 18.9 MB split-K partials
__device__ __half    g_xh[NN * INDIM];          // 4 MB  x hi fp16
__device__ __half    g_xl[NN * INDIM];          // 4 MB  x lo fp16
__device__ __half    g_wh[DTOT * INDIM];        // 64 KB W hi fp16
__device__ __half    g_wl[DTOT * INDIM];        // 64 KB W lo fp16

__device__ __forceinline__ uint32_t smem_u32(const void* p) {
    uint32_t a;
    asm("{ .reg .u64 t; cvta.to.shared.u64 t, %1; cvt.u32.u64 %0, t; }" : "=r"(a) : "l"(p));
    return a;
}
#define SWZ(off) ((off) ^ (((off) >> 3) & 0x70))

// ordered-uint encoding for float atomicMax
__device__ __forceinline__ unsigned enc_f(float f) {
    unsigned b = __float_as_uint(f);
    return (b & 0x80000000u) ? ~b : (b | 0x80000000u);
}
__device__ __forceinline__ float dec_f(unsigned k) {
    return (k & 0x80000000u) ? __uint_as_float(k & 0x7FFFFFFFu) : __uint_as_float(~k);
}

// ======================= k0: split x, W into fp16 hi/lo =======================
__global__ void __launch_bounds__(256) k0_convert(const float* __restrict__ x,
                                                 const float* __restrict__ W) {
    int g = blockIdx.x * 256 + threadIdx.x;          // over 2M/4 float4s of x
    if (g == 0) { g_maxkey[0] = 0u; g_maxkey[1] = 0u; }
    {
        float4 v = ((const float4*)x)[g];
        __half h0 = __float2half(v.x), h1 = __float2half(v.y),
               h2 = __float2half(v.z), h3 = __float2half(v.w);
        uint2 hh = make_uint2((uint32_t)__half_as_ushort(h0) | ((uint32_t)__half_as_ushort(h1) << 16),
                              (uint32_t)__half_as_ushort(h2) | ((uint32_t)__half_as_ushort(h3) << 16));
        ((uint2*)g_xh)[g] = hh;
        __half l0 = __float2half(v.x - __half2float(h0));
        __half l1 = __float2half(v.y - __half2float(h1));
        __half l2 = __float2half(v.z - __half2float(h2));
        __half l3 = __float2half(v.w - __half2float(h3));
        uint2 ll = make_uint2((uint32_t)__half_as_ushort(l0) | ((uint32_t)__half_as_ushort(l1) << 16),
                              (uint32_t)__half_as_ushort(l2) | ((uint32_t)__half_as_ushort(l3) << 16));
        ((uint2*)g_xl)[g] = ll;
    }
    if (g < DTOT * INDIM / 4) {
        float4 v = ((const float4*)W)[g];
        __half h0 = __float2half(v.x), h1 = __float2half(v.y),
               h2 = __float2half(v.z), h3 = __float2half(v.w);
        uint2 hh = make_uint2((uint32_t)__half_as_ushort(h0) | ((uint32_t)__half_as_ushort(h1) << 16),
                              (uint32_t)__half_as_ushort(h2) | ((uint32_t)__half_as_ushort(h3) << 16));
        ((uint2*)g_wh)[g] = hh;
        __half l0 = __float2half(v.x - __half2float(h0));
        __half l1 = __float2half(v.y - __half2float(h1));
        __half l2 = __float2half(v.z - __half2float(h2));
        __half l3 = __float2half(v.w - __half2float(h3));
        uint2 ll = make_uint2((uint32_t)__half_as_ushort(l0) | ((uint32_t)__half_as_ushort(l1) << 16),
                              (uint32_t)__half_as_ushort(l2) | ((uint32_t)__half_as_ushort(l3) << 16));
        ((uint2*)g_wl)[g] = ll;
    }
}

// ======================= k1: h = x @ W^T (fp16 hi/lo tensor cores) =======================
// grid 128 = 64 m-tiles x 2 n-tiles. CTA: 128 rows x 64 cols, K=256 all resident.
#define K1_SMEM 196608
__global__ void __launch_bounds__(256) k1_h_gemm(const int dummy) {
    extern __shared__ char s1[];
    uint32_t sb = smem_u32(s1);
    int tid = threadIdx.x, lane = tid & 31, wid = tid >> 5;
    int wm = wid & 3, wn = wid >> 2;      // 4(M) x 2(N)
    int lt = lane >> 3, lr = lane & 7;
    int mtile = blockIdx.x >> 1, ntile = blockIdx.x & 1;
    int i0 = mtile * 128, n0 = ntile * 64;

#pragma unroll
    for (int i = 0; i < 8; ++i) {
        int q = tid + i * 256;                  // 2048 chunks
        int k = q >> 9, r = (q >> 3) & 63, c = q & 7;
        uint32_t sw = SWZ((uint32_t)(r * 128 + c * 16));
        const void* sh = (const char*)g_wh + ((size_t)(n0 + r) * INDIM + k * 64 + c * 8) * 2;
        const void* sl = (const char*)g_wl + ((size_t)(n0 + r) * INDIM + k * 64 + c * 8) * 2;
        asm volatile("cp.async.cg.shared.global [%0], [%1], 16;" :: "r"(sb + k * 8192 + sw), "l"(sh));
        asm volatile("cp.async.cg.shared.global [%0], [%1], 16;" :: "r"(sb + 32768 + k * 8192 + sw), "l"(sl));
    }
#pragma unroll
    for (int i = 0; i < 16; ++i) {
        int q = tid + i * 256;                  // 4096 chunks
        int k = q >> 10, r = (q >> 3) & 127, c = q & 7;
        uint32_t sw = SWZ((uint32_t)(r * 128 + c * 16));
        const void* sh = (const char*)g_xh + ((size_t)(i0 + r) * INDIM + k * 64 + c * 8) * 2;
        const void* sl = (const char*)g_xl + ((size_t)(i0 + r) * INDIM + k * 64 + c * 8) * 2;
        asm volatile("cp.async.cg.shared.global [%0], [%1], 16;" :: "r"(sb + 65536 + k * 16384 + sw), "l"(sh));
        asm volatile("cp.async.cg.shared.global [%0], [%1], 16;" :: "r"(sb + 131072 + k * 16384 + sw), "l"(sl));
    }
    asm volatile("cp.async.commit_group;" ::: "memory");
    asm volatile("cp.async.wait_group 0;" ::: "memory");
    __syncthreads();

    uint32_t arow[2], brow[2];
#pragma unroll
    for (int mf = 0; mf < 2; ++mf)
        arow[mf] = (uint32_t)((wm * 32 + mf * 16 + (lt & 1) * 8 + lr) * 128 + (lt >> 1) * 16);
#pragma unroll
    for (int g4 = 0; g4 < 2; ++g4)
        brow[g4] = (uint32_t)((wn * 32 + g4 * 16 + (lt >> 1) * 8 + lr) * 128 + (lt & 1) * 16);

    float acc[2][4][4];
#pragma unroll
    for (int mf = 0; mf < 2; ++mf)
#pragma unroll
        for (int nf = 0; nf < 4; ++nf)
#pragma unroll
            for (int q = 0; q < 4; ++q) acc[mf][nf][q] = 0.f;

#pragma unroll
    for (int kc = 0; kc < 4; ++kc) {
        uint32_t Wh = sb + kc * 8192, Wl = sb + 32768 + kc * 8192;
        uint32_t Xh = sb + 65536 + kc * 16384, Xl = sb + 131072 + kc * 16384;
#pragma unroll
        for (int s = 0; s < 4; ++s) {
            uint32_t kb = (uint32_t)(s * 32);
            uint32_t ah[2][4], al[2][4];
#pragma unroll
            for (int mf = 0; mf < 2; ++mf) {
                asm volatile("ldmatrix.sync.aligned.m8n8.x4.shared.b16 {%0,%1,%2,%3}, [%4];"
                    : "=r"(ah[mf][0]), "=r"(ah[mf][1]), "=r"(ah[mf][2]), "=r"(ah[mf][3])
                    : "r"(Xh + SWZ(arow[mf] + kb)));
                asm volatile("ldmatrix.sync.aligned.m8n8.x4.shared.b16 {%0,%1,%2,%3}, [%4];"
                    : "=r"(al[mf][0]), "=r"(al[mf][1]), "=r"(al[mf][2]), "=r"(al[mf][3])
                    : "r"(Xl + SWZ(arow[mf] + kb)));
            }
            uint32_t bh[4][2], bl[4][2];
#pragma unroll
            for (int g4 = 0; g4 < 2; ++g4) {
                asm volatile("ldmatrix.sync.aligned.m8n8.x4.shared.b16 {%0,%1,%2,%3}, [%4];"
                    : "=r"(bh[2 * g4][0]), "=r"(bh[2 * g4][1]),
                      "=r"(bh[2 * g4 + 1][0]), "=r"(bh[2 * g4 + 1][1])
                    : "r"(Wh + SWZ(brow[g4] + kb)));
                asm volatile("ldmatrix.sync.aligned.m8n8.x4.shared.b16 {%0,%1,%2,%3}, [%4];"
                    : "=r"(bl[2 * g4][0]), "=r"(bl[2 * g4][1]),
                      "=r"(bl[2 * g4 + 1][0]), "=r"(bl[2 * g4 + 1][1])
                    : "r"(Wl + SWZ(brow[g4] + kb)));
            }
#define K1MMA(AF, BF)                                                                   \
            asm volatile("mma.sync.aligned.m16n8k16.row.col.f32.f16.f16.f32 "           \
                "{%0,%1,%2,%3}, {%4,%5,%6,%7}, {%8,%9}, {%0,%1,%2,%3};"                 \
                : "+f"(acc[mf][nf][0]), "+f"(acc[mf][nf][1]),                           \
                  "+f"(acc[mf][nf][2]), "+f"(acc[mf][nf][3])                            \
                : "r"(AF[mf][0]), "r"(AF[mf][1]), "r"(AF[mf][2]), "r"(AF[mf][3]),       \
                  "r"(BF[nf][0]), "r"(BF[nf][1]))
#pragma unroll
            for (int mf = 0; mf < 2; ++mf)
#pragma unroll
                for (int nf = 0; nf < 4; ++nf) {
                    K1MMA(ah, bh);
                    K1MMA(al, bh);
                    K1MMA(ah, bl);
                }
#undef K1MMA
        }
    }

    int r0 = i0 + wm * 32 + (lane >> 2);
    int c0 = n0 + wn * 32 + (lane & 3) * 2;
#pragma unroll
    for (int mf = 0; mf < 2; ++mf)
#pragma unroll
        for (int nf = 0; nf < 4; ++nf) {
            int row = r0 + mf * 16, col = c0 + nf * 8;
            *(float2*)(g_h + (size_t)row * DTOT + col) =
                make_float2(acc[mf][nf][0], acc[mf][nf][1]);
            *(float2*)(g_h + (size_t)(row + 8) * DTOT + col) =
                make_float2(acc[mf][nf][2], acc[mf][nf][3]);
        }
}

// ======================= k2a: er[j,h] (warp per node) + global max =======================
__global__ void __launch_bounds__(256) k2a_er(const float* __restrict__ attn_r) {
    int tid = threadIdx.x, lane = tid & 31, w = tid >> 5;
    int j = blockIdx.x * 8 + w;
    float4 hv = *(const float4*)(g_h + (size_t)j * DTOT + lane * 4);
    float4 av = *(const float4*)(attn_r + lane * 4);
    float p = hv.x * av.x + hv.y * av.y + hv.z * av.z + hv.w * av.w;
#pragma unroll
    for (int o = 8; o; o >>= 1) p += __shfl_xor_sync(0xFFFFFFFFu, p, o);
    // lanes 0-15 hold er0(j), lanes 16-31 hold er1(j)
    __shared__ float s0[8], s1[8];
    if (lane == 0)  { g_er[j] = p;      s0[w] = p; }
    if (lane == 16) { g_er[NN + j] = p; s1[w] = p; }
    __syncthreads();
    if (tid == 0) {
        float m0 = s0[0], m1 = s1[0];
#pragma unroll
        for (int q = 1; q < 8; ++q) { m0 = fmaxf(m0, s0[q]); m1 = fmaxf(m1, s1[q]); }
        atomicMax(&g_maxkey[0], enc_f(m0));
        atomicMax(&g_maxkey[1], enc_f(m1));
    }
}

// ======================= k2b: G^T = exp(er - max) * h  (fp16, smem transpose) =======================
#define J2B 32
__global__ void __launch_bounds__(256) k2b_build_g() {
    __shared__ float sh[J2B][133];          // pitch 133: 133 mod 32 = 5, conflict-free col reads
    __shared__ float sE0[J2B], sE1[J2B];
    int tid = threadIdx.x;
    int j0 = blockIdx.x * J2B;
    // coalesced load of 32 h-rows (1024 float4)
#pragma unroll
    for (int i = 0; i < 4; ++i) {
        int q = tid + i * 256;
        int r = q >> 5, c4 = q & 31;
        float4 v = *(const float4*)(g_h + (size_t)(j0 + r) * DTOT + c4 * 4);
        sh[r][c4 * 4 + 0] = v.x; sh[r][c4 * 4 + 1] = v.y;
        sh[r][c4 * 4 + 2] = v.z; sh[r][c4 * 4 + 3] = v.w;
    }
    if (tid < J2B) {
        float m0 = dec_f(g_maxkey[0]), m1 = dec_f(g_maxkey[1]);
        sE0[tid] = expf(g_er[j0 + tid] - m0);
        sE1[tid] = expf(g_er[NN + j0 + tid] - m1);
    }
    __syncthreads();
    int w = tid >> 5, lane = tid & 31;
    // warps over columns, lanes over j -> 64B contiguous stores
#pragma unroll
    for (int cc = 0; cc < 16; ++cc) {
        int c = w * 16 + cc;
        float E = (c < 64) ? sE0[lane] : sE1[lane];
        g_g[(size_t)c * NN + j0 + lane] = __float2half(E * sh[lane][c]);
    }
    // rows 128..143: 2 rows per warp
    {
        int r0 = 128 + w * 2;
        g_g[(size_t)r0 * NN + j0 + lane] =
            (r0 == 128) ? __float2half(sE0[lane]) : __float2half(0.f);
        g_g[(size_t)(r0 + 1) * NN + j0 + lane] =
            (r0 + 1 == 129) ? __float2half(sE1[lane]) : __float2half(0.f);
    }
}

// ======================= k3: [num|den] = f16(adj) @ G  (R9 structure, all cp.async) =======================
#define APITCH 272
#define ABYTES 34816
#define STAGEB 53248
#define NSTG   2
#define SMEM3  (NSTG * STAGEB)

__device__ __forceinline__ void stage_load(uint32_t Sb, const int* __restrict__ adj,
                                           int i0, int j0, int tid) {
    uint32_t Ab = Sb, Bb = Sb + ABYTES;
#pragma unroll
    for (int i = 0; i < 8; ++i) {
        int q = tid + i * 256;
        int r = q >> 4, ch = q & 15;
        uint32_t dst = Ab + (uint32_t)(r * APITCH + ch * 16);
        const void* src = adj + (size_t)(i0 + r) * NN + j0 + ch * 4;
        asm volatile("cp.async.cg.shared.global [%0], [%1], 16;" :: "r"(dst), "l"(src));
    }
#pragma unroll
    for (int i = 0; i < 5; ++i) {
        int q = tid + i * 256;
        if (q < NCP * 8) {
            int n = q >> 3, c = q & 7;
            uint32_t dst = Bb + SWZ((uint32_t)(n * 128 + c * 16));
            const void* src = (const char*)g_g + ((size_t)n * NN + j0) * 2 + c * 16;
            asm volatile("cp.async.cg.shared.global [%0], [%1], 16;" :: "r"(dst), "l"(src));
        }
    }
    asm volatile("cp.async.commit_group;" ::: "memory");
}

__device__ __forceinline__ void compute_iter(uint32_t Ab, uint32_t Bb,
                                             float acc[2][9][4],
                                             uint32_t aoff,
                                             const uint32_t brow4[4],
                                             uint32_t brow2) {
#pragma unroll
    for (int s = 0; s < 4; ++s) {
        uint32_t kb = s * 32;
        uint32_t ka = s * 64;
        uint32_t a[2][4];
#pragma unroll
        for (int mf = 0; mf < 2; ++mf) {
            uint32_t base = Ab + aoff + (uint32_t)(mf * 16 * APITCH) + ka;
            uint32_t x0, y0, x1, y1, x2, y2, x3, y3;
            asm("ld.shared.v2.u32 {%0,%1}, [%2];" : "=r"(x0), "=r"(y0) : "r"(base));
            asm("ld.shared.v2.u32 {%0,%1}, [%2];" : "=r"(x1), "=r"(y1) : "r"(base + 8 * APITCH));
            asm("ld.shared.v2.u32 {%0,%1}, [%2];" : "=r"(x2), "=r"(y2) : "r"(base + 32));
            asm("ld.shared.v2.u32 {%0,%1}, [%2];" : "=r"(x3), "=r"(y3) : "r"(base + 8 * APITCH + 32));
            a[mf][0] = (x0 | (y0 << 16)) * 0x3C00u;
            a[mf][1] = (x1 | (y1 << 16)) * 0x3C00u;
            a[mf][2] = (x2 | (y2 << 16)) * 0x3C00u;
            a[mf][3] = (x3 | (y3 << 16)) * 0x3C00u;
        }
        uint32_t b[9][2];
#pragma unroll
        for (int g4 = 0; g4 < 4; ++g4) {
            uint32_t bd = Bb + SWZ(brow4[g4] + kb);
            asm volatile("ldmatrix.sync.aligned.m8n8.x4.shared.b16 {%0,%1,%2,%3}, [%4];"
                : "=r"(b[2 * g4][0]), "=r"(b[2 * g4][1]),
                  "=r"(b[2 * g4 + 1][0]), "=r"(b[2 * g4 + 1][1]) : "r"(bd));
        }
        {
            uint32_t bd = Bb + SWZ(brow2 + kb);
            asm volatile("ldmatrix.sync.aligned.m8n8.x2.shared.b16 {%0,%1}, [%2];"
                : "=r"(b[8][0]), "=r"(b[8][1]) : "r"(bd));
        }
#pragma unroll
        for (int mf = 0; mf < 2; ++mf)
#pragma unroll
            for (int nf = 0; nf < 9; ++nf)
                asm volatile(
                    "mma.sync.aligned.m16n8k16.row.col.f32.f16.f16.f32 "
                    "{%0,%1,%2,%3}, {%4,%5,%6,%7}, {%8,%9}, {%0,%1,%2,%3};"
                    : "+f"(acc[mf][nf][0]), "+f"(acc[mf][nf][1]),
                      "+f"(acc[mf][nf][2]), "+f"(acc[mf][nf][3])
                    : "r"(a[mf][0]), "r"(a[mf][1]), "r"(a[mf][2]), "r"(a[mf][3]),
                      "r"(b[nf][0]), "r"(b[nf][1]));
    }
}

__global__ void __launch_bounds__(256, 2) k3_adj_gemm(const int* __restrict__ adj) {
    extern __shared__ char sm3[];
    uint32_t sb = smem_u32(sm3);
    int tid = threadIdx.x, lane = tid & 31, wid = tid >> 5;
    int wm = wid & 3, wn = wid >> 2;          // 4 (M) x 2 (N) warps
    int lt = lane >> 3, lr = lane & 7;
    int mtile = blockIdx.x >> 2, sp = blockIdx.x & 3;
    int i0 = mtile * MT, jb = sp * KSPLIT;

    uint32_t aoff = (uint32_t)((wm * 32 + (lane >> 2)) * APITCH + (lane & 3) * 8);
    uint32_t brow4[4], brow2;
#pragma unroll
    for (int g4 = 0; g4 < 4; ++g4)
        brow4[g4] = (uint32_t)((wn * 72 + g4 * 16 + (lt >> 1) * 8 + lr) * 128 + (lt & 1) * 16);
    brow2 = (uint32_t)((wn * 72 + 64 + lr) * 128 + (lt & 1) * 16);

    float acc[2][9][4];
#pragma unroll
    for (int mf = 0; mf < 2; ++mf)
#pragma unroll
        for (int nf = 0; nf < 9; ++nf)
#pragma unroll
            for (int q = 0; q < 4; ++q) acc[mf][nf][q] = 0.f;

    stage_load(sb + 0 * STAGEB, adj, i0, jb + 0 * KT, tid);
    stage_load(sb + 1 * STAGEB, adj, i0, jb + 1 * KT, tid);

    for (int it = 0; it < NKI; ++it) {
        if (it < NKI - 1)
            asm volatile("cp.async.wait_group 1;" ::: "memory");
        else
            asm volatile("cp.async.wait_group 0;" ::: "memory");
        __syncthreads();
        uint32_t Sb = sb + (it & 1) * STAGEB;
        compute_iter(Sb, Sb + ABYTES, acc, aoff, brow4, brow2);
        if (it + 2 < NKI) {
            __syncthreads();   // all warps done reading this buffer
            stage_load(Sb, adj, i0, jb + (it + 2) * KT, tid);
        }
    }

    int r0 = i0 + wm * 32 + (lane >> 2);
    int c0 = wn * 72 + (lane & 3) * 2;
    float* base = g_part + (size_t)sp * NN * NCP;
#pragma unroll
    for (int mf = 0; mf < 2; ++mf)
#pragma unroll
        for (int nf = 0; nf < 9; ++nf) {
            int row = r0 + mf * 16, col = c0 + nf * 8;
            *(float2*)(base + (size_t)row * NCP + col) =
                make_float2(acc[mf][nf][0], acc[mf][nf][1]);
            *(float2*)(base + (size_t)(row + 8) * NCP + col) =
                make_float2(acc[mf][nf][2], acc[mf][nf][3]);
        }
}

// ======================= k4: combine splits + divide =======================
__global__ void __launch_bounds__(256) k4_finalize(float* __restrict__ out) {
    int g = blockIdx.x * 256 + threadIdx.x;   // over 8192*128
    int i = g >> 7, c = g & 127;
    int hh = c >> 6;
    float num = 0.f, den = 0.f;
#pragma unroll
    for (int s = 0; s < NSPLIT; ++s) {
        const float* p = g_part + ((size_t)s * NN + i) * NCP;
        num += p[c];
        den += p[128 + hh];
    }
    out[g] = num / den;
}

// ======================= launch =======================
extern "C" void kernel_launch(void* const* d_in, const int* in_sizes, int n_in,
                              void* d_out, int out_size) {
    (void)in_sizes; (void)n_in; (void)out_size;
    const float* x      = (const float*)d_in[0];
    const int*   adj    = (const int*)d_in[1];
    const float* W      = (const float*)d_in[2];
    // d_in[3] = attn_l : cancels in the softmax over j — unused
    const float* attn_r = (const float*)d_in[4];
    float* out = (float*)d_out;

    cudaFuncSetAttribute(k1_h_gemm, cudaFuncAttributeMaxDynamicSharedMemorySize, K1_SMEM);
    cudaFuncSetAttribute(k3_adj_gemm, cudaFuncAttributeMaxDynamicSharedMemorySize, SMEM3);

    k0_convert<<<2048, 256>>>(x, W);
    k1_h_gemm<<<128, 256, K1_SMEM>>>(0);
    k2a_er<<<1024, 256>>>(attn_r);
    k2b_build_g<<<256, 256>>>();
    k3_adj_gemm<<<256, 256, SMEM3>>>(adj);
    k4_finalize<<<4096, 256>>>(out);
}